// round 5
// baseline (speedup 1.0000x reference)
#include <cuda_runtime.h>
#include <cuda_bf16.h>
#include <cstdint>

#define TOK   32768
#define CDIM  256
#define KCODE 8192
#define BM    128
#define TAU   0.02f

// ---------------- scratch (device globals; no allocation allowed) ----------------
__device__ __nv_bfloat16 g_nch[KCODE * CDIM];   // negated codebook, bf16 high part
__device__ __nv_bfloat16 g_ncl[KCODE * CDIM];   // negated codebook, bf16 low part
__device__ float         g_cn[KCODE];           // 0.5 * ||e||^2 (fp64-accurate)
__device__ int           g_ind[TOK];            // argmin indices
__device__ int           g_rlist[TOK];          // near-tie tokens needing rescue
__device__ int           g_nrescue;             // count of rescue tokens

// ---------------- kernel 1: NCHW -> [T,C] transpose (writes 'data' output) -------
__global__ void k_transpose(const float* __restrict__ in, float* __restrict__ data)
{
    __shared__ float tile[32][33];
    const int c0 = blockIdx.x * 32;     // 8 c-tiles
    const int h  = blockIdx.y;          // 32
    const int n  = blockIdx.z;          // 32
    {
        const int wx = threadIdx.x & 31, cy = threadIdx.x >> 5;
        #pragma unroll
        for (int i = 0; i < 4; i++) {
            const int c = cy + i * 8;
            tile[c][wx] = in[(((size_t)n * CDIM + c0 + c) * 32 + h) * 32 + wx];
        }
    }
    __syncthreads();
    {
        const int c = threadIdx.x & 31, wq = threadIdx.x >> 5;
        #pragma unroll
        for (int i = 0; i < 4; i++) {
            const int w = wq + i * 8;
            data[(size_t)(n * 1024 + h * 32 + w) * CDIM + c0 + c] = tile[c][w];
        }
    }
}

// ---------------- kernel 2: codebook prep: fp64 half-norms + negated bf16 hi/lo --
__global__ void k_codeprep(const float* __restrict__ cb)
{
    if (blockIdx.x == 0 && threadIdx.x == 0) g_nrescue = 0;   // reset per launch
    const int warp = threadIdx.x >> 5, lane = threadIdx.x & 31;
    const int code = blockIdx.x * 8 + warp;                 // grid 1024 * 8 warps
    const float* row = cb + (size_t)code * CDIM;
    double s = 0.0;
    #pragma unroll
    for (int i = 0; i < 8; i++) {
        const int c = lane + i * 32;
        const float e = row[c];
        s += (double)e * (double)e;
        const __nv_bfloat16 hb = __float2bfloat16(-e);
        g_nch[(size_t)code * CDIM + c] = hb;
        g_ncl[(size_t)code * CDIM + c] = __float2bfloat16(-e - __bfloat162float(hb));
    }
    #pragma unroll
    for (int o = 16; o > 0; o >>= 1) s += __shfl_xor_sync(0xffffffffu, s, o);
    if (lane == 0) g_cn[code] = (float)(0.5 * s);
}

// ---------------- mma helpers ----------------------------------------------------
__device__ __forceinline__ void ldsm4(uint32_t addr, uint32_t& r0, uint32_t& r1,
                                      uint32_t& r2, uint32_t& r3)
{
    asm volatile("ldmatrix.sync.aligned.m8n8.x4.shared.b16 {%0,%1,%2,%3}, [%4];"
                 : "=r"(r0), "=r"(r1), "=r"(r2), "=r"(r3) : "r"(addr));
}
__device__ __forceinline__ void mma16816(float* c, const uint32_t* a,
                                         uint32_t b0, uint32_t b1)
{
    asm volatile("mma.sync.aligned.m16n8k16.row.col.f32.bf16.bf16.f32 "
                 "{%0,%1,%2,%3}, {%4,%5,%6,%7}, {%8,%9}, {%0,%1,%2,%3};"
                 : "+f"(c[0]), "+f"(c[1]), "+f"(c[2]), "+f"(c[3])
                 : "r"(a[0]), "r"(a[1]), "r"(a[2]), "r"(a[3]), "r"(b0), "r"(b1));
}

// smem layout (bytes):
//   Ah : 128 x 264 bf16  = 67584   @ 0
//   Al : 67584                     @ 67584
//   B  : 2 bufs x (Bh 128x72 bf16 = 18432, Bl 18432) @ 135168, buf stride 36864
#define OFF_AL   67584u
#define OFF_B   135168u
#define B_BUFSZ  36864u
#define B_LOFF   18432u
#define SMEM_SZ 208896

// ---------------- kernel 3: fused 3xBF16 GEMM + argmin(+margin) -------------------
__global__ void __launch_bounds__(256, 1)
k_gemm_argmin(const float* __restrict__ data)
{
    extern __shared__ char smem[];
    const int tid = threadIdx.x, lane = tid & 31, warp = tid >> 5;
    const int blk = blockIdx.x;                       // M tile (128 rows)

    // ---- load A tile (fp32) and convert to bf16 hi/lo in smem ----
    {
        const float4* src = (const float4*)(data + (size_t)blk * BM * CDIM);
        __nv_bfloat16* Ah = (__nv_bfloat16*)smem;
        __nv_bfloat16* Al = (__nv_bfloat16*)(smem + OFF_AL);
        #pragma unroll
        for (int i = 0; i < 32; i++) {
            const int u = tid + i * 256;
            const int row = u >> 6, c4 = u & 63;
            const float4 v = src[u];
            union { __nv_bfloat16 b[4]; uint2 q; } ph, pl;
            const float f[4] = {v.x, v.y, v.z, v.w};
            #pragma unroll
            for (int j = 0; j < 4; j++) {
                const __nv_bfloat16 hb = __float2bfloat16(f[j]);
                ph.b[j] = hb;
                pl.b[j] = __float2bfloat16(f[j] - __bfloat162float(hb));
            }
            *(uint2*)(Ah + row * 264 + c4 * 4) = ph.q;
            *(uint2*)(Al + row * 264 + c4 * 4) = pl.q;
        }
    }

    const uint32_t sbase = (uint32_t)__cvta_generic_to_shared(smem);
    const int a_row = warp * 16 + ((lane >> 3) & 1) * 8 + (lane & 7);
    const int a_c8  = (lane >> 4) * 8;
    const uint32_t aH_base = sbase + (uint32_t)(a_row * 264 + a_c8) * 2u;
    const uint32_t aL_base = aH_base + OFF_AL;
    const int b_row = (lane >> 4) * 8 + (lane & 7);
    const int b_c8  = ((lane >> 3) & 1) * 8;
    const uint32_t bT_base = sbase + OFF_B + (uint32_t)(b_row * 72 + b_c8) * 2u;

    const int      g_off        = (tid >> 3) * 32 + (tid & 7);      // uint4 index
    const uint32_t st_byte_base = (uint32_t)((tid >> 3) * 144 + (tid & 7) * 16);

    uint4 rh[4], rl[4];

    auto LOADG = [&](int g) {
        const int chunk = g >> 2, s = g & 3;
        const uint4* bh = (const uint4*)(g_nch + (size_t)chunk * 128 * CDIM + s * 64);
        const uint4* bl = (const uint4*)(g_ncl + (size_t)chunk * 128 * CDIM + s * 64);
        #pragma unroll
        for (int i = 0; i < 4; i++) {
            rh[i] = bh[g_off + i * 1024];
            rl[i] = bl[g_off + i * 1024];
        }
    };
    auto STORE = [&](int buf) {
        char* B = smem + OFF_B + (uint32_t)buf * B_BUFSZ;
        #pragma unroll
        for (int i = 0; i < 4; i++) {
            *(uint4*)(B + st_byte_base + i * 4608)          = rh[i];
            *(uint4*)(B + B_LOFF + st_byte_base + i * 4608) = rl[i];
        }
    };

    float acc[16][4];
    float v1[2] = {3.4e38f, 3.4e38f};   // best
    float v2[2] = {3.4e38f, 3.4e38f};   // runner-up value
    int   i1[2] = {0, 0};

    LOADG(0);
    STORE(0);

    for (int g = 0; g < 256; ++g) {                  // 64 chunks x 4 k-slices
        const int buf = g & 1, chunk = g >> 2, s = g & 3;
        __syncthreads();
        if (g + 1 < 256) LOADG(g + 1);

        if (s == 0) {
            #pragma unroll
            for (int ct = 0; ct < 16; ++ct) {
                acc[ct][0] = 0.f; acc[ct][1] = 0.f;
                acc[ct][2] = 0.f; acc[ct][3] = 0.f;
            }
        }

        const uint32_t aH = aH_base + (uint32_t)(s * 128);
        const uint32_t aL = aL_base + (uint32_t)(s * 128);
        const uint32_t bB = bT_base + (uint32_t)buf * B_BUFSZ;

        #pragma unroll
        for (int kk = 0; kk < 4; ++kk) {
            uint32_t ah[4], al[4];
            ldsm4(aH + kk * 32, ah[0], ah[1], ah[2], ah[3]);
            ldsm4(aL + kk * 32, al[0], al[1], al[2], al[3]);
            #pragma unroll
            for (int p = 0; p < 8; ++p) {
                uint32_t bh0, bh1, bh2, bh3, bl0, bl1, bl2, bl3;
                const uint32_t baddr = bB + (uint32_t)(p * 2304 + kk * 32);
                ldsm4(baddr,          bh0, bh1, bh2, bh3);
                ldsm4(baddr + B_LOFF, bl0, bl1, bl2, bl3);
                mma16816(acc[2 * p],     ah, bh0, bh1);   // xh * eh
                mma16816(acc[2 * p + 1], ah, bh2, bh3);
                mma16816(acc[2 * p],     ah, bl0, bl1);   // xh * el
                mma16816(acc[2 * p + 1], ah, bl2, bl3);
                mma16816(acc[2 * p],     al, bh0, bh1);   // xl * eh
                mma16816(acc[2 * p + 1], al, bh2, bh3);
            }
        }

        if (s == 3) {        // chunk epilogue: score = 0.5||e||^2 - x.e, track top-2
            #pragma unroll
            for (int ct = 0; ct < 16; ++ct) {
                const int nb = chunk * 128 + ct * 8 + (lane & 3) * 2;
                const float2 c2 = *(const float2*)(g_cn + nb);
                const float sc[4] = { acc[ct][0] + c2.x, acc[ct][1] + c2.y,
                                      acc[ct][2] + c2.x, acc[ct][3] + c2.y };
                #pragma unroll
                for (int j = 0; j < 4; j++) {
                    const int h = j >> 1;
                    const float v = sc[j];
                    const int idx = nb + (j & 1);
                    if (v < v1[h]) { v2[h] = v1[h]; v1[h] = v; i1[h] = idx; }
                    else if (v < v2[h]) { v2[h] = v; }
                }
            }
        }
        if (g + 1 < 256) STORE(buf ^ 1);
    }

    // reduce (top-2) across the 4 lanes sharing a row; write index + rescue flag
    #pragma unroll
    for (int h = 0; h < 2; ++h) {
        float a1 = v1[h], a2 = v2[h]; int ai = i1[h];
        #pragma unroll
        for (int off = 1; off <= 2; off <<= 1) {
            const float o1 = __shfl_xor_sync(0xffffffffu, a1, off);
            const int   oi = __shfl_xor_sync(0xffffffffu, ai, off);
            const float o2 = __shfl_xor_sync(0xffffffffu, a2, off);
            if (o1 < a1 || (o1 == a1 && oi < ai)) {
                a2 = fminf(a1, o2); a1 = o1; ai = oi;
            } else {
                a2 = fminf(o1, a2);
            }
        }
        if ((lane & 3) == 0) {
            const int row = blk * BM + warp * 16 + h * 8 + (lane >> 2);
            g_ind[row] = ai;
            if (a2 - a1 < TAU) {
                const int p = atomicAdd(&g_nrescue, 1);
                if (p < TOK) g_rlist[p] = row;
            }
        }
    }
}

// ---------------- kernel 3.5: rescue near-ties with ref-emulated fp32 dist -------
// Emulates the reference: dist = fl( fl(A - 2*G) + C ) with A = sum of fl(x^2),
// G = x.e to ~1e-7 (Kahan + exact products), C = fl(||e||^2). Lowest-index tie-break.
__device__ __forceinline__ void nadd(float& s, float& c, float v)
{
    const float t = s + v;
    c += (fabsf(s) >= fabsf(v)) ? ((s - t) + v) : ((v - t) + s);
    s = t;
}

__global__ void __launch_bounds__(256) k_rescue(const float* __restrict__ data,
                                                const float* __restrict__ cb)
{
    __shared__ float xs[CDIM];
    __shared__ float bv[256];
    __shared__ int   bi[256];
    const int tid = threadIdx.x;
    int nr = g_nrescue; if (nr > TOK) nr = TOK;

    for (int it = blockIdx.x; it < nr; it += gridDim.x) {
        const int t = g_rlist[it];
        __syncthreads();
        xs[tid] = data[(size_t)t * CDIM + tid];
        __syncthreads();

        // A = exact sum of fp32-rounded squares (emulates ref's fp32 row-norm)
        float sA = 0.f, cA = 0.f;
        #pragma unroll 8
        for (int i = 0; i < CDIM; i++) {
            const float p = __fmul_rn(xs[i], xs[i]);
            nadd(sA, cA, p);
        }
        const float A = sA + cA;

        float best = 3.4e38f; int bidx = 0x7fffffff;
        for (int j = 0; j < KCODE / 256; j++) {
            const int k = tid + j * 256;
            const float* e = cb + (size_t)k * CDIM;
            float sG = 0.f, cG = 0.f;
            #pragma unroll 8
            for (int i = 0; i < CDIM; i++) {
                const float p  = __fmul_rn(xs[i], e[i]);
                const float pe = __fmaf_rn(xs[i], e[i], -p);
                nadd(sG, cG, p);
                cG += pe;
            }
            const float G = sG + cG;
            const float B = __fmul_rn(2.0f, G);
            const float C = __fmul_rn(2.0f, g_cn[k]);           // exact x2 scale
            const float d = __fadd_rn(__fsub_rn(A, B), C);      // ref rounding
            if (d < best || (d == best && k < bidx)) { best = d; bidx = k; }
        }

        bv[tid] = best; bi[tid] = bidx;
        __syncthreads();
        for (int o = 128; o > 0; o >>= 1) {
            if (tid < o) {
                const float ov = bv[tid + o]; const int oi = bi[tid + o];
                if (ov < bv[tid] || (ov == bv[tid] && oi < bi[tid])) {
                    bv[tid] = ov; bi[tid] = oi;
                }
            }
            __syncthreads();
        }
        if (tid == 0) g_ind[t] = bi[0];
    }
}

// ---------------- kernel 4: gather -> quantize + quantize_detach -----------------
__global__ void k_gather(const float* __restrict__ cb, float* __restrict__ out)
{
    const int id  = blockIdx.x * 256 + threadIdx.x;  // 0 .. TOK*64-1 (float4 units)
    const int row = id >> 6, c4 = id & 63;
    const int ind = g_ind[row];
    const float4 v = ((const float4*)cb)[(size_t)ind * 64 + c4];
    float4* o4 = (float4*)out;
    o4[(size_t)row * 64 + c4] = v;                         // quantize
    o4[(size_t)TOK * 64 + (size_t)row * 64 + c4] = v;      // quantize_detach (== quantize)
}

// ---------------- launcher --------------------------------------------------------
extern "C" void kernel_launch(void* const* d_in, const int* in_sizes, int n_in,
                              void* d_out, int out_size)
{
    const float* input = (const float*)d_in[0];   // [32,256,32,32] fp32
    const float* cb    = (const float*)d_in[1];   // [8192,256] fp32
    float* out  = (float*)d_out;                  // [quantize | detach | data], each [32768,256]
    float* data = out + (size_t)2 * TOK * CDIM;

    cudaFuncSetAttribute(k_gemm_argmin, cudaFuncAttributeMaxDynamicSharedMemorySize, SMEM_SZ);

    k_transpose  <<<dim3(8, 32, 32), 256>>>(input, data);
    k_codeprep   <<<1024, 256>>>(cb);
    k_gemm_argmin<<<256, 256, SMEM_SZ>>>(data);
    k_rescue     <<<256, 256>>>(data, cb);
    k_gather     <<<8192, 256>>>(cb, out);
}